// round 3
// baseline (speedup 1.0000x reference)
#include <cuda_runtime.h>

#define SEQ 4096
#define HIDDEN 2048
#define NH 16
#define NKV 8
#define HD 128
#define WINDOW 1024
#define SCALING 0.08838834764831845f  /* 128^-0.5 */
#define SOFTCAP 50.0f

// ---------------- scratch (no allocations allowed) ----------------
__device__ float g_Q[SEQ * NH * HD];    // 32 MB
__device__ float g_K[SEQ * NKV * HD];   // 16 MB
__device__ float g_V[SEQ * NKV * HD];   // 16 MB
__device__ float g_AO[SEQ * NH * HD];   // 32 MB

// ---------------- classic register-blocked SGEMM ----------------
// C[M,N] = A[M,K] @ B[K,N], all row-major. BM=BN=128, BK=8, 256 thr, 8x8/thread.
#define BM 128
#define BN 128
#define BK 8

__global__ __launch_bounds__(256) void sgemm_kernel(
    int M, int N, int K,
    const float* __restrict__ A, const float* __restrict__ B,
    float* __restrict__ C)
{
    __shared__ float As[BK][BM];
    __shared__ float Bs[BK][BN];

    const int tid = threadIdx.x;
    const int brow = blockIdx.y;
    const int bcol = blockIdx.x;

    const float* Ab = A + (size_t)brow * BM * K;
    const float* Bb = B + (size_t)bcol * BN;
    float* Cb = C + (size_t)brow * BM * N + (size_t)bcol * BN;

    const int arow = tid >> 1;          // 0..127
    const int acol = (tid & 1) * 4;     // 0 or 4
    const int brow_l = tid >> 5;        // 0..7
    const int bcol_l = (tid & 31) * 4;  // 0..124

    const int ty = (tid >> 4) * 8;      // 0..120
    const int tx = (tid & 15) * 8;      // 0..120

    float acc[8][8];
#pragma unroll
    for (int i = 0; i < 8; i++)
#pragma unroll
        for (int j = 0; j < 8; j++) acc[i][j] = 0.f;

    for (int k0 = 0; k0 < K; k0 += BK) {
        float4 a4 = *(const float4*)(Ab + (size_t)arow * K + k0 + acol);
        As[acol + 0][arow] = a4.x;
        As[acol + 1][arow] = a4.y;
        As[acol + 2][arow] = a4.z;
        As[acol + 3][arow] = a4.w;
        float4 b4 = *(const float4*)(Bb + (size_t)(k0 + brow_l) * N + bcol_l);
        *(float4*)&Bs[brow_l][bcol_l] = b4;
        __syncthreads();

#pragma unroll
        for (int k = 0; k < BK; k++) {
            float ar[8], br[8];
            *(float4*)&ar[0] = *(const float4*)&As[k][ty];
            *(float4*)&ar[4] = *(const float4*)&As[k][ty + 4];
            *(float4*)&br[0] = *(const float4*)&Bs[k][tx];
            *(float4*)&br[4] = *(const float4*)&Bs[k][tx + 4];
#pragma unroll
            for (int i = 0; i < 8; i++)
#pragma unroll
                for (int j = 0; j < 8; j++) acc[i][j] += ar[i] * br[j];
        }
        __syncthreads();
    }

#pragma unroll
    for (int i = 0; i < 8; i++) {
#pragma unroll
        for (int j = 0; j < 8; j += 4) {
            float4 v = make_float4(acc[i][j], acc[i][j + 1], acc[i][j + 2], acc[i][j + 3]);
            *(float4*)(Cb + (size_t)(ty + i) * N + tx + j) = v;
        }
    }
}

// ---------------- RoPE (in place on g_Q, g_K) ----------------
__global__ void rope_kernel(const float* __restrict__ cosb,
                            const float* __restrict__ sinb)
{
    const int s = blockIdx.x;
    const float* cs = cosb + (size_t)s * HD;
    const float* sn = sinb + (size_t)s * HD;
    for (int idx = threadIdx.x; idx < (NH + NKV) * 64; idx += blockDim.x) {
        const int head = idx >> 6;
        const int d = idx & 63;
        const float c = cs[d];
        const float sv = sn[d];
        float* base;
        if (head < NH)
            base = g_Q + (size_t)s * (NH * HD) + head * HD;
        else
            base = g_K + (size_t)s * (NKV * HD) + (head - NH) * HD;
        const float x1 = base[d];
        const float x2 = base[d + 64];
        base[d]      = x1 * c - x2 * sv;
        base[d + 64] = x2 * c + x1 * sv;
    }
}

// ---------------- windowed attention, no-max softcapped softmax ----------------
// grid (S/64, NH), 256 threads. Bq=Bk=64.
// Thread (ty=tid>>4, tx=tid&15): scores for rows 4ty+i (i<4), keys tx+16j (j<4);
// PV: rows 4ty+i, d-cols 8tx..8tx+7.
#define BQ 64
#define BKT 64
#define QS_STRIDE 132   // mod 32 = 4 -> the 2 distinct warp rows land in distinct banks
#define KS_STRIDE 132
#define PS_STRIDE 68

extern __shared__ float sm_attn[];

__global__ __launch_bounds__(256) void attn_kernel(float* __restrict__ AO)
{
    float* Qs = sm_attn;                    // 64*132
    float* Ks = Qs + BQ * QS_STRIDE;        // 64*132
    float* Vs = Ks + BKT * KS_STRIDE;       // 64*128
    float* Ps = Vs + BKT * HD;              // 64*68

    const int qb = blockIdx.x;
    const int h = blockIdx.y;
    const int kvh = h >> 1;                 // N_REP = 2
    const int q0 = qb * BQ;
    const int tid = threadIdx.x;
    const int ty = tid >> 4;
    const int tx = tid & 15;

    // load Q tile (rows q0..q0+63, head h)
    const float* Qg = g_Q + (size_t)q0 * (NH * HD) + h * HD;
    for (int i = tid; i < BQ * HD / 4; i += 256) {
        const int r = i >> 5;
        const int d4 = (i & 31) * 4;
        float4 v = *(const float4*)(Qg + (size_t)r * (NH * HD) + d4);
        *(float4*)&Qs[r * QS_STRIDE + d4] = v;
    }

    float o[4][8];
    float l[4];
#pragma unroll
    for (int i = 0; i < 4; i++) {
        l[i] = 0.f;
#pragma unroll
        for (int j = 0; j < 8; j++) o[i][j] = 0.f;
    }

    int lo = q0 - (WINDOW - 1);
    if (lo < 0) lo = 0;
    const int kb_lo = lo / BKT;

    for (int kb = kb_lo; kb <= qb; kb++) {
        const int k0 = kb * BKT;
        const float* Kg = g_K + (size_t)k0 * (NKV * HD) + kvh * HD;
        const float* Vg = g_V + (size_t)k0 * (NKV * HD) + kvh * HD;

        __syncthreads();  // previous iteration done reading Ks/Vs (and Qs store on iter 0)
        for (int i = tid; i < BKT * HD / 4; i += 256) {
            const int r = i >> 5;
            const int d4 = (i & 31) * 4;
            float4 kv = *(const float4*)(Kg + (size_t)r * (NKV * HD) + d4);
            *(float4*)&Ks[r * KS_STRIDE + d4] = kv;
            float4 vv = *(const float4*)(Vg + (size_t)r * (NKV * HD) + d4);
            *(float4*)&Vs[r * HD + d4] = vv;
        }
        __syncthreads();

        // ----- scores: S = Q K^T -----
        float acc[4][4];
#pragma unroll
        for (int i = 0; i < 4; i++)
#pragma unroll
            for (int j = 0; j < 4; j++) acc[i][j] = 0.f;

#pragma unroll 4
        for (int d = 0; d < HD; d++) {
            float a[4], b[4];
#pragma unroll
            for (int i = 0; i < 4; i++) a[i] = Qs[(4 * ty + i) * QS_STRIDE + d];
#pragma unroll
            for (int j = 0; j < 4; j++) b[j] = Ks[(tx + 16 * j) * KS_STRIDE + d];
#pragma unroll
            for (int i = 0; i < 4; i++)
#pragma unroll
                for (int j = 0; j < 4; j++) acc[i][j] += a[i] * b[j];
        }

        // ----- softcap + window mask + exp; stash P; accumulate row sums -----
#pragma unroll
        for (int i = 0; i < 4; i++) {
            const int rg = q0 + 4 * ty + i;
            float lpart = 0.f;
#pragma unroll
            for (int j = 0; j < 4; j++) {
                const int kg = k0 + tx + 16 * j;
                float p = 0.f;
                if (kg <= rg && rg - kg < WINDOW) {
                    float sc = tanhf(acc[i][j] * (SCALING / SOFTCAP)) * SOFTCAP;
                    p = __expf(sc);   // bounded by e^50: no max-tracking needed
                }
                Ps[(4 * ty + i) * PS_STRIDE + tx + 16 * j] = p;
                lpart += p;
            }
            // sum across the 16 lanes sharing ty (tx = bits 0..3 of lane)
            lpart += __shfl_xor_sync(0xffffffffu, lpart, 1);
            lpart += __shfl_xor_sync(0xffffffffu, lpart, 2);
            lpart += __shfl_xor_sync(0xffffffffu, lpart, 4);
            lpart += __shfl_xor_sync(0xffffffffu, lpart, 8);
            l[i] += lpart;
        }
        __syncwarp();  // P rows 4ty..4ty+3 are produced & consumed within this warp

        // ----- O += P @ V -----
        for (int j = 0; j < BKT; j++) {
            float pr[4];
#pragma unroll
            for (int i = 0; i < 4; i++) pr[i] = Ps[(4 * ty + i) * PS_STRIDE + j];
            float4 v0 = *(const float4*)&Vs[j * HD + 8 * tx];
            float4 v1 = *(const float4*)&Vs[j * HD + 8 * tx + 4];
#pragma unroll
            for (int i = 0; i < 4; i++) {
                o[i][0] += pr[i] * v0.x; o[i][1] += pr[i] * v0.y;
                o[i][2] += pr[i] * v0.z; o[i][3] += pr[i] * v0.w;
                o[i][4] += pr[i] * v1.x; o[i][5] += pr[i] * v1.y;
                o[i][6] += pr[i] * v1.z; o[i][7] += pr[i] * v1.w;
            }
        }
    }

    // normalize & write [s][h*128+d] (matches (0,2,1,3)-transpose reshape)
#pragma unroll
    for (int i = 0; i < 4; i++) {
        const float inv = 1.0f / l[i];
        float* outp = AO + (size_t)(q0 + 4 * ty + i) * (NH * HD) + h * HD + 8 * tx;
#pragma unroll
        for (int j = 0; j < 8; j++) outp[j] = o[i][j] * inv;
    }
}

// ---------------- launch ----------------
extern "C" void kernel_launch(void* const* d_in, const int* in_sizes, int n_in,
                              void* d_out, int out_size)
{
    const float* hs   = (const float*)d_in[0];
    const float* cosb = (const float*)d_in[1];
    const float* sinb = (const float*)d_in[2];
    // d_in[3] attention_mask: window+causal computed analytically, never read
    const float* Wq = (const float*)d_in[4];
    const float* Wk = (const float*)d_in[5];
    const float* Wv = (const float*)d_in[6];
    const float* Wo = (const float*)d_in[7];
    float* out = (float*)d_out;

    float *qp, *kp, *vp, *aop;
    cudaGetSymbolAddress((void**)&qp, g_Q);
    cudaGetSymbolAddress((void**)&kp, g_K);
    cudaGetSymbolAddress((void**)&vp, g_V);
    cudaGetSymbolAddress((void**)&aop, g_AO);

    dim3 blk(256);
    // QKV projections
    sgemm_kernel<<<dim3((NH * HD) / BN, SEQ / BM), blk>>>(SEQ, NH * HD, HIDDEN, hs, Wq, qp);
    sgemm_kernel<<<dim3((NKV * HD) / BN, SEQ / BM), blk>>>(SEQ, NKV * HD, HIDDEN, hs, Wk, kp);
    sgemm_kernel<<<dim3((NKV * HD) / BN, SEQ / BM), blk>>>(SEQ, NKV * HD, HIDDEN, hs, Wv, vp);

    // RoPE on Q and K
    rope_kernel<<<SEQ, 256>>>(cosb, sinb);

    // attention
    const size_t smem_bytes =
        (BQ * QS_STRIDE + BKT * KS_STRIDE + BKT * HD + BQ * PS_STRIDE) * sizeof(float);
    cudaFuncSetAttribute(attn_kernel, cudaFuncAttributeMaxDynamicSharedMemorySize,
                         (int)smem_bytes);
    attn_kernel<<<dim3(SEQ / BQ, NH), 256, smem_bytes>>>(aop);

    // output projection
    sgemm_kernel<<<dim3(HIDDEN / BN, SEQ / BM), blk>>>(SEQ, HIDDEN, NH * HD, aop, Wo, out);
}

// round 4
// speedup vs baseline: 1.6411x; 1.6411x over previous
#include <cuda_runtime.h>
#include <cstdint>

#define SEQ 4096
#define HIDDEN 2048
#define NH 16
#define NKV 8
#define HD 128
#define WINDOW 1024
#define SCALING 0.08838834764831845f  /* 128^-0.5 */
#define SOFTCAP 50.0f

// ---------------- scratch (no allocations allowed) ----------------
__device__ float g_Q[SEQ * NH * HD];    // 32 MB
__device__ float g_K[SEQ * NKV * HD];   // 16 MB
__device__ float g_V[SEQ * NKV * HD];   // 16 MB
__device__ float g_AO[SEQ * NH * HD];   // 32 MB

// ---------------- TF32 tensor-core GEMM ----------------
// C[M,N] = A[M,K] @ B[K,N], row-major. 128x128x16 tile, 256 thr (8 warps),
// warp grid 2(M) x 4(N), warp tile 64x32 via mma.m16n8k8 (4x4 frags).
#define AS_S 136   // mod 32 = 8 -> frag loads conflict-free (bank = 8*tig + gid)
#define BS_S 136

__device__ __forceinline__ uint32_t f2tf32(float x) {
    uint32_t r;
    asm("cvt.rna.tf32.f32 %0, %1;" : "=r"(r) : "f"(x));
    return r;
}

__global__ __launch_bounds__(256, 2) void gemm_tf32(
    int M, int N, int K,
    const float* __restrict__ A, const float* __restrict__ B,
    float* __restrict__ C)
{
    __shared__ uint32_t As[16 * AS_S];   // [k][m], swizzled: m index ^16 when (k&4)
    __shared__ uint32_t Bs[16 * BS_S];   // [k][n]

    const int tid  = threadIdx.x;
    const int lane = tid & 31;
    const int gid  = lane >> 2;          // 0..7
    const int tig  = lane & 3;           // 0..3
    const int wid  = tid >> 5;
    const int wm0  = (wid >> 2) * 64;    // 0 or 64
    const int wn0  = (wid & 3) * 32;     // 0,32,64,96

    const float* Ab = A + (size_t)blockIdx.y * 128 * K;
    const float* Bb = B + (size_t)blockIdx.x * 128;
    float* Cb = C + (size_t)blockIdx.y * 128 * N + (size_t)blockIdx.x * 128;

    // A loader: row ar (0..127), k-chunks akc..akc+3 and akc+8..akc+11
    const int ar  = tid >> 1;
    const int akc = (tid & 1) * 4;
    // B loader: row br (0..15), col chunks bc..bc+3 and bc+64..bc+67
    const int br = tid >> 4;
    const int bc = (tid & 15) * 4;

    float4 pa0 = *(const float4*)(Ab + (size_t)ar * K + akc);
    float4 pa1 = *(const float4*)(Ab + (size_t)ar * K + akc + 8);
    float4 pb0 = *(const float4*)(Bb + (size_t)br * N + bc);
    float4 pb1 = *(const float4*)(Bb + (size_t)br * N + bc + 64);

    float c[4][4][4];
#pragma unroll
    for (int mi = 0; mi < 4; mi++)
#pragma unroll
        for (int ni = 0; ni < 4; ni++)
#pragma unroll
            for (int r = 0; r < 4; r++) c[mi][ni][r] = 0.f;

    for (int k0 = 0; k0 < K; k0 += 16) {
        __syncthreads();
        // store A (transposed, swizzled). k = akc+j has k&4==0 iff akc==0 branch;
        // swizzle row index ^16 when (k & 4).
        {
            const float av[8] = {pa0.x, pa0.y, pa0.z, pa0.w, pa1.x, pa1.y, pa1.z, pa1.w};
#pragma unroll
            for (int j = 0; j < 4; j++) {
                int k1 = akc + j;          // 0..7
                int k2 = akc + 8 + j;      // 8..15
                int r1 = (k1 & 4) ? (ar ^ 16) : ar;
                int r2 = (k2 & 4) ? (ar ^ 16) : ar;
                As[k1 * AS_S + r1] = f2tf32(av[j]);
                As[k2 * AS_S + r2] = f2tf32(av[4 + j]);
            }
            const float bv[8] = {pb0.x, pb0.y, pb0.z, pb0.w, pb1.x, pb1.y, pb1.z, pb1.w};
#pragma unroll
            for (int j = 0; j < 4; j++) {
                Bs[br * BS_S + bc + j]      = f2tf32(bv[j]);
                Bs[br * BS_S + bc + 64 + j] = f2tf32(bv[4 + j]);
            }
        }
        __syncthreads();

        if (k0 + 16 < K) {
            pa0 = *(const float4*)(Ab + (size_t)ar * K + k0 + 16 + akc);
            pa1 = *(const float4*)(Ab + (size_t)ar * K + k0 + 16 + akc + 8);
            pb0 = *(const float4*)(Bb + (size_t)(k0 + 16 + br) * N + bc);
            pb1 = *(const float4*)(Bb + (size_t)(k0 + 16 + br) * N + bc + 64);
        }

#pragma unroll
        for (int kk = 0; kk < 2; kk++) {
            const int kb = kk * 8;
            uint32_t aR[4][4], bR[4][2];
#pragma unroll
            for (int mi = 0; mi < 4; mi++) {
                const int m0 = wm0 + mi * 16;
                // rows kb+tig (k&4==0): no swizzle; rows kb+tig+4 (k&4): ^16
                aR[mi][0] = As[(kb + tig) * AS_S + m0 + gid];
                aR[mi][1] = As[(kb + tig) * AS_S + m0 + gid + 8];
                aR[mi][2] = As[(kb + tig + 4) * AS_S + ((m0 + gid) ^ 16)];
                aR[mi][3] = As[(kb + tig + 4) * AS_S + ((m0 + gid + 8) ^ 16)];
            }
#pragma unroll
            for (int ni = 0; ni < 4; ni++) {
                const int n0 = wn0 + ni * 8;
                bR[ni][0] = Bs[(kb + tig) * BS_S + n0 + gid];
                bR[ni][1] = Bs[(kb + tig + 4) * BS_S + n0 + gid];
            }
#pragma unroll
            for (int mi = 0; mi < 4; mi++)
#pragma unroll
                for (int ni = 0; ni < 4; ni++) {
                    asm volatile(
                        "mma.sync.aligned.m16n8k8.row.col.f32.tf32.tf32.f32 "
                        "{%0,%1,%2,%3}, {%4,%5,%6,%7}, {%8,%9}, {%0,%1,%2,%3};"
                        : "+f"(c[mi][ni][0]), "+f"(c[mi][ni][1]),
                          "+f"(c[mi][ni][2]), "+f"(c[mi][ni][3])
                        : "r"(aR[mi][0]), "r"(aR[mi][1]), "r"(aR[mi][2]), "r"(aR[mi][3]),
                          "r"(bR[ni][0]), "r"(bR[ni][1]));
                }
        }
    }

    // epilogue: c0,c1 -> (row gid, cols 2*tig..2*tig+1); c2,c3 -> row gid+8
#pragma unroll
    for (int mi = 0; mi < 4; mi++) {
        const int m0 = wm0 + mi * 16;
#pragma unroll
        for (int ni = 0; ni < 4; ni++) {
            const int n0 = wn0 + ni * 8 + tig * 2;
            *(float2*)(Cb + (size_t)(m0 + gid) * N + n0) =
                make_float2(c[mi][ni][0], c[mi][ni][1]);
            *(float2*)(Cb + (size_t)(m0 + gid + 8) * N + n0) =
                make_float2(c[mi][ni][2], c[mi][ni][3]);
        }
    }
}

// ---------------- RoPE (in place on g_Q, g_K) ----------------
__global__ void rope_kernel(const float* __restrict__ cosb,
                            const float* __restrict__ sinb)
{
    const int s = blockIdx.x;
    const float* cs = cosb + (size_t)s * HD;
    const float* sn = sinb + (size_t)s * HD;
    for (int idx = threadIdx.x; idx < (NH + NKV) * 64; idx += blockDim.x) {
        const int head = idx >> 6;
        const int d = idx & 63;
        const float c = cs[d];
        const float sv = sn[d];
        float* base;
        if (head < NH)
            base = g_Q + (size_t)s * (NH * HD) + head * HD;
        else
            base = g_K + (size_t)s * (NKV * HD) + (head - NH) * HD;
        const float x1 = base[d];
        const float x2 = base[d + 64];
        base[d]      = x1 * c - x2 * sv;
        base[d + 64] = x2 * c + x1 * sv;
    }
}

// ---------------- windowed attention, no-max softcapped softmax ----------------
#define BQ 64
#define BKT 64
#define QS_STRIDE 132
#define KS_STRIDE 132
#define PS_STRIDE 68

extern __shared__ float sm_attn[];

__global__ __launch_bounds__(256) void attn_kernel(float* __restrict__ AO)
{
    float* Qs = sm_attn;                    // 64*132
    float* Ks = Qs + BQ * QS_STRIDE;        // 64*132
    float* Vs = Ks + BKT * KS_STRIDE;       // 64*128
    float* Ps = Vs + BKT * HD;              // 64*68

    const int qb = blockIdx.x;
    const int h = blockIdx.y;
    const int kvh = h >> 1;                 // N_REP = 2
    const int q0 = qb * BQ;
    const int tid = threadIdx.x;
    const int ty = tid >> 4;
    const int tx = tid & 15;

    const float* Qg = g_Q + (size_t)q0 * (NH * HD) + h * HD;
    for (int i = tid; i < BQ * HD / 4; i += 256) {
        const int r = i >> 5;
        const int d4 = (i & 31) * 4;
        float4 v = *(const float4*)(Qg + (size_t)r * (NH * HD) + d4);
        *(float4*)&Qs[r * QS_STRIDE + d4] = v;
    }

    float o[4][8];
    float l[4];
#pragma unroll
    for (int i = 0; i < 4; i++) {
        l[i] = 0.f;
#pragma unroll
        for (int j = 0; j < 8; j++) o[i][j] = 0.f;
    }

    int lo = q0 - (WINDOW - 1);
    if (lo < 0) lo = 0;
    const int kb_lo = lo / BKT;

    for (int kb = kb_lo; kb <= qb; kb++) {
        const int k0 = kb * BKT;
        const float* Kg = g_K + (size_t)k0 * (NKV * HD) + kvh * HD;
        const float* Vg = g_V + (size_t)k0 * (NKV * HD) + kvh * HD;

        __syncthreads();
        for (int i = tid; i < BKT * HD / 4; i += 256) {
            const int r = i >> 5;
            const int d4 = (i & 31) * 4;
            float4 kv = *(const float4*)(Kg + (size_t)r * (NKV * HD) + d4);
            *(float4*)&Ks[r * KS_STRIDE + d4] = kv;
            float4 vv = *(const float4*)(Vg + (size_t)r * (NKV * HD) + d4);
            *(float4*)&Vs[r * HD + d4] = vv;
        }
        __syncthreads();

        float acc[4][4];
#pragma unroll
        for (int i = 0; i < 4; i++)
#pragma unroll
            for (int j = 0; j < 4; j++) acc[i][j] = 0.f;

#pragma unroll 4
        for (int d = 0; d < HD; d++) {
            float a[4], b[4];
#pragma unroll
            for (int i = 0; i < 4; i++) a[i] = Qs[(4 * ty + i) * QS_STRIDE + d];
#pragma unroll
            for (int j = 0; j < 4; j++) b[j] = Ks[(tx + 16 * j) * KS_STRIDE + d];
#pragma unroll
            for (int i = 0; i < 4; i++)
#pragma unroll
                for (int j = 0; j < 4; j++) acc[i][j] += a[i] * b[j];
        }

#pragma unroll
        for (int i = 0; i < 4; i++) {
            const int rg = q0 + 4 * ty + i;
            float lpart = 0.f;
#pragma unroll
            for (int j = 0; j < 4; j++) {
                const int kg = k0 + tx + 16 * j;
                float p = 0.f;
                if (kg <= rg && rg - kg < WINDOW) {
                    float sc = tanhf(acc[i][j] * (SCALING / SOFTCAP)) * SOFTCAP;
                    p = __expf(sc);
                }
                Ps[(4 * ty + i) * PS_STRIDE + tx + 16 * j] = p;
                lpart += p;
            }
            lpart += __shfl_xor_sync(0xffffffffu, lpart, 1);
            lpart += __shfl_xor_sync(0xffffffffu, lpart, 2);
            lpart += __shfl_xor_sync(0xffffffffu, lpart, 4);
            lpart += __shfl_xor_sync(0xffffffffu, lpart, 8);
            l[i] += lpart;
        }
        __syncwarp();

        for (int j = 0; j < BKT; j++) {
            float pr[4];
#pragma unroll
            for (int i = 0; i < 4; i++) pr[i] = Ps[(4 * ty + i) * PS_STRIDE + j];
            float4 v0 = *(const float4*)&Vs[j * HD + 8 * tx];
            float4 v1 = *(const float4*)&Vs[j * HD + 8 * tx + 4];
#pragma unroll
            for (int i = 0; i < 4; i++) {
                o[i][0] += pr[i] * v0.x; o[i][1] += pr[i] * v0.y;
                o[i][2] += pr[i] * v0.z; o[i][3] += pr[i] * v0.w;
                o[i][4] += pr[i] * v1.x; o[i][5] += pr[i] * v1.y;
                o[i][6] += pr[i] * v1.z; o[i][7] += pr[i] * v1.w;
            }
        }
    }

#pragma unroll
    for (int i = 0; i < 4; i++) {
        const float inv = 1.0f / l[i];
        float* outp = AO + (size_t)(q0 + 4 * ty + i) * (NH * HD) + h * HD + 8 * tx;
#pragma unroll
        for (int j = 0; j < 8; j++) outp[j] = o[i][j] * inv;
    }
}

// ---------------- launch ----------------
extern "C" void kernel_launch(void* const* d_in, const int* in_sizes, int n_in,
                              void* d_out, int out_size)
{
    const float* hs   = (const float*)d_in[0];
    const float* cosb = (const float*)d_in[1];
    const float* sinb = (const float*)d_in[2];
    // d_in[3] attention_mask: computed analytically, never read
    const float* Wq = (const float*)d_in[4];
    const float* Wk = (const float*)d_in[5];
    const float* Wv = (const float*)d_in[6];
    const float* Wo = (const float*)d_in[7];
    float* out = (float*)d_out;

    float *qp, *kp, *vp, *aop;
    cudaGetSymbolAddress((void**)&qp, g_Q);
    cudaGetSymbolAddress((void**)&kp, g_K);
    cudaGetSymbolAddress((void**)&vp, g_V);
    cudaGetSymbolAddress((void**)&aop, g_AO);

    dim3 blk(256);
    gemm_tf32<<<dim3((NH * HD) / 128, SEQ / 128), blk>>>(SEQ, NH * HD, HIDDEN, hs, Wq, qp);
    gemm_tf32<<<dim3((NKV * HD) / 128, SEQ / 128), blk>>>(SEQ, NKV * HD, HIDDEN, hs, Wk, kp);
    gemm_tf32<<<dim3((NKV * HD) / 128, SEQ / 128), blk>>>(SEQ, NKV * HD, HIDDEN, hs, Wv, vp);

    rope_kernel<<<SEQ, 256>>>(cosb, sinb);

    const size_t smem_bytes =
        (BQ * QS_STRIDE + BKT * KS_STRIDE + BKT * HD + BQ * PS_STRIDE) * sizeof(float);
    cudaFuncSetAttribute(attn_kernel, cudaFuncAttributeMaxDynamicSharedMemorySize,
                         (int)smem_bytes);
    attn_kernel<<<dim3(SEQ / BQ, NH), 256, smem_bytes>>>(aop);

    gemm_tf32<<<dim3(HIDDEN / 128, SEQ / 128), blk>>>(SEQ, HIDDEN, NH * HD, aop, Wo, out);
}

// round 7
// speedup vs baseline: 2.4967x; 1.5214x over previous
#include <cuda_runtime.h>
#include <cstdint>

#define SEQ 4096
#define HIDDEN 2048
#define NH 16
#define NKV 8
#define HD 128
#define WINDOW 1024
#define SCALING 0.08838834764831845f  /* 128^-0.5 */
#define SOFTCAP 50.0f

// ---------------- scratch (no allocations allowed) ----------------
__device__ float g_Q[SEQ * NH * HD];    // 32 MB
__device__ float g_K[SEQ * NKV * HD];   // 16 MB
__device__ float g_V[SEQ * NKV * HD];   // 16 MB
__device__ float g_AO[SEQ * NH * HD];   // 32 MB

__device__ __forceinline__ uint32_t f2tf32(float x) {
    uint32_t r;
    asm("cvt.rna.tf32.f32 %0, %1;" : "=r"(r) : "f"(x));
    return r;
}

// ---------------- TF32 tensor-core GEMM (unchanged from R3) ----------------
#define AS_S 136
#define BS_S 136

__global__ __launch_bounds__(256, 2) void gemm_tf32(
    int M, int N, int K,
    const float* __restrict__ A, const float* __restrict__ B,
    float* __restrict__ C)
{
    __shared__ uint32_t As[16 * AS_S];
    __shared__ uint32_t Bs[16 * BS_S];

    const int tid  = threadIdx.x;
    const int lane = tid & 31;
    const int gid  = lane >> 2;
    const int tig  = lane & 3;
    const int wid  = tid >> 5;
    const int wm0  = (wid >> 2) * 64;
    const int wn0  = (wid & 3) * 32;

    const float* Ab = A + (size_t)blockIdx.y * 128 * K;
    const float* Bb = B + (size_t)blockIdx.x * 128;
    float* Cb = C + (size_t)blockIdx.y * 128 * N + (size_t)blockIdx.x * 128;

    const int ar  = tid >> 1;
    const int akc = (tid & 1) * 4;
    const int br = tid >> 4;
    const int bc = (tid & 15) * 4;

    float4 pa0 = *(const float4*)(Ab + (size_t)ar * K + akc);
    float4 pa1 = *(const float4*)(Ab + (size_t)ar * K + akc + 8);
    float4 pb0 = *(const float4*)(Bb + (size_t)br * N + bc);
    float4 pb1 = *(const float4*)(Bb + (size_t)br * N + bc + 64);

    float c[4][4][4];
#pragma unroll
    for (int mi = 0; mi < 4; mi++)
#pragma unroll
        for (int ni = 0; ni < 4; ni++)
#pragma unroll
            for (int r = 0; r < 4; r++) c[mi][ni][r] = 0.f;

    for (int k0 = 0; k0 < K; k0 += 16) {
        __syncthreads();
        {
            const float av[8] = {pa0.x, pa0.y, pa0.z, pa0.w, pa1.x, pa1.y, pa1.z, pa1.w};
#pragma unroll
            for (int j = 0; j < 4; j++) {
                int k1 = akc + j;
                int k2 = akc + 8 + j;
                int r1 = (k1 & 4) ? (ar ^ 16) : ar;
                int r2 = (k2 & 4) ? (ar ^ 16) : ar;
                As[k1 * AS_S + r1] = f2tf32(av[j]);
                As[k2 * AS_S + r2] = f2tf32(av[4 + j]);
            }
            const float bv[8] = {pb0.x, pb0.y, pb0.z, pb0.w, pb1.x, pb1.y, pb1.z, pb1.w};
#pragma unroll
            for (int j = 0; j < 4; j++) {
                Bs[br * BS_S + bc + j]      = f2tf32(bv[j]);
                Bs[br * BS_S + bc + 64 + j] = f2tf32(bv[4 + j]);
            }
        }
        __syncthreads();

        if (k0 + 16 < K) {
            pa0 = *(const float4*)(Ab + (size_t)ar * K + k0 + 16 + akc);
            pa1 = *(const float4*)(Ab + (size_t)ar * K + k0 + 16 + akc + 8);
            pb0 = *(const float4*)(Bb + (size_t)(k0 + 16 + br) * N + bc);
            pb1 = *(const float4*)(Bb + (size_t)(k0 + 16 + br) * N + bc + 64);
        }

#pragma unroll
        for (int kk = 0; kk < 2; kk++) {
            const int kb = kk * 8;
            uint32_t aR[4][4], bR[4][2];
#pragma unroll
            for (int mi = 0; mi < 4; mi++) {
                const int m0 = wm0 + mi * 16;
                aR[mi][0] = As[(kb + tig) * AS_S + m0 + gid];
                aR[mi][1] = As[(kb + tig) * AS_S + m0 + gid + 8];
                aR[mi][2] = As[(kb + tig + 4) * AS_S + ((m0 + gid) ^ 16)];
                aR[mi][3] = As[(kb + tig + 4) * AS_S + ((m0 + gid + 8) ^ 16)];
            }
#pragma unroll
            for (int ni = 0; ni < 4; ni++) {
                const int n0 = wn0 + ni * 8;
                bR[ni][0] = Bs[(kb + tig) * BS_S + n0 + gid];
                bR[ni][1] = Bs[(kb + tig + 4) * BS_S + n0 + gid];
            }
#pragma unroll
            for (int mi = 0; mi < 4; mi++)
#pragma unroll
                for (int ni = 0; ni < 4; ni++) {
                    asm volatile(
                        "mma.sync.aligned.m16n8k8.row.col.f32.tf32.tf32.f32 "
                        "{%0,%1,%2,%3}, {%4,%5,%6,%7}, {%8,%9}, {%0,%1,%2,%3};"
                        : "+f"(c[mi][ni][0]), "+f"(c[mi][ni][1]),
                          "+f"(c[mi][ni][2]), "+f"(c[mi][ni][3])
                        : "r"(aR[mi][0]), "r"(aR[mi][1]), "r"(aR[mi][2]), "r"(aR[mi][3]),
                          "r"(bR[ni][0]), "r"(bR[ni][1]));
                }
        }
    }

#pragma unroll
    for (int mi = 0; mi < 4; mi++) {
        const int m0 = wm0 + mi * 16;
#pragma unroll
        for (int ni = 0; ni < 4; ni++) {
            const int n0 = wn0 + ni * 8 + tig * 2;
            *(float2*)(Cb + (size_t)(m0 + gid) * N + n0) =
                make_float2(c[mi][ni][0], c[mi][ni][1]);
            *(float2*)(Cb + (size_t)(m0 + gid + 8) * N + n0) =
                make_float2(c[mi][ni][2], c[mi][ni][3]);
        }
    }
}

// ---------------- RoPE (in place on g_Q, g_K) ----------------
__global__ void rope_kernel(const float* __restrict__ cosb,
                            const float* __restrict__ sinb)
{
    const int s = blockIdx.x;
    const float* cs = cosb + (size_t)s * HD;
    const float* sn = sinb + (size_t)s * HD;
    for (int idx = threadIdx.x; idx < (NH + NKV) * 64; idx += blockDim.x) {
        const int head = idx >> 6;
        const int d = idx & 63;
        const float c = cs[d];
        const float sv = sn[d];
        float* base;
        if (head < NH)
            base = g_Q + (size_t)s * (NH * HD) + head * HD;
        else
            base = g_K + (size_t)s * (NKV * HD) + (head - NH) * HD;
        const float x1 = base[d];
        const float x2 = base[d + 64];
        base[d]      = x1 * c - x2 * sv;
        base[d + 64] = x2 * c + x1 * sv;
    }
}

// ---------------- TF32 tensor-core flash attention ----------------
// grid (SEQ/64, NH), 128 threads (4 warps). Warp w owns Q rows 16w..16w+15.
// Q A-frags persistent in regs. K (stride 132) and V (stride 136) tf32 in smem.
// P staged per-warp through smem (stride 68) -> only __syncwarp between QK and PV.
#define KS_AT 132   // mod 32 = 4
#define VS_AT 136   // mod 32 = 8
#define PS_AT 68    // mod 32 = 4

extern __shared__ float sm_attn[];

__global__ __launch_bounds__(128, 2) void attn_mma(float* __restrict__ AO)
{
    float*    Qs = sm_attn;                                  // 64*132 (aliases Ks)
    uint32_t* Ks = (uint32_t*)sm_attn;                       // 64*132
    uint32_t* Vs = (uint32_t*)(sm_attn + 64 * KS_AT);        // 64*136
    uint32_t* Ps = (uint32_t*)(sm_attn + 64 * (KS_AT + VS_AT)); // 64*68

    const int qb = blockIdx.x;
    const int h  = blockIdx.y;
    const int kvh = h >> 1;
    const int q0 = qb * 64;
    const int tid = threadIdx.x;
    const int lane = tid & 31;
    const int w = tid >> 5;
    const int gid = lane >> 2;
    const int tig = lane & 3;

    // ---- load Q tile to smem (raw fp32), coalesced ----
    const float* Qg = g_Q + (size_t)q0 * (NH * HD) + h * HD;
    for (int i = tid; i < 64 * HD / 4; i += 128) {
        const int r = i >> 5;
        const int d4 = (i & 31) * 4;
        float4 v = *(const float4*)(Qg + (size_t)r * (NH * HD) + d4);
        *(float4*)&Qs[r * KS_AT + d4] = v;
    }
    __syncthreads();

    // ---- Q A-frags (persistent): 16 k-chunks x 4 regs ----
    uint32_t qa[16][4];
    const int qr0 = 16 * w + gid;
#pragma unroll
    for (int c = 0; c < 16; c++) {
        qa[c][0] = f2tf32(Qs[qr0 * KS_AT + 8 * c + tig]);
        qa[c][1] = f2tf32(Qs[(qr0 + 8) * KS_AT + 8 * c + tig]);
        qa[c][2] = f2tf32(Qs[qr0 * KS_AT + 8 * c + tig + 4]);
        qa[c][3] = f2tf32(Qs[(qr0 + 8) * KS_AT + 8 * c + tig + 4]);
    }

    float oacc[16][4];
#pragma unroll
    for (int ni = 0; ni < 16; ni++)
#pragma unroll
        for (int r = 0; r < 4; r++) oacc[ni][r] = 0.f;
    float lsum[2] = {0.f, 0.f};

    int lo = q0 - (WINDOW - 1);
    if (lo < 0) lo = 0;
    const int kb_lo = lo / 64;

    for (int kb = kb_lo; kb <= qb; kb++) {
        const int k0 = kb * 64;
        const float* Kg = g_K + (size_t)k0 * (NKV * HD) + kvh * HD;
        const float* Vg = g_V + (size_t)k0 * (NKV * HD) + kvh * HD;

        __syncthreads();  // prior tile's PV reads done; Q frag reads done (iter 0)
        for (int i = tid; i < 64 * HD / 4; i += 128) {
            const int r = i >> 5;
            const int d4 = (i & 31) * 4;
            float4 kv = *(const float4*)(Kg + (size_t)r * (NKV * HD) + d4);
            uint4 kt = make_uint4(f2tf32(kv.x), f2tf32(kv.y), f2tf32(kv.z), f2tf32(kv.w));
            *(uint4*)&Ks[r * KS_AT + d4] = kt;
            float4 vv = *(const float4*)(Vg + (size_t)r * (NKV * HD) + d4);
            uint4 vt = make_uint4(f2tf32(vv.x), f2tf32(vv.y), f2tf32(vv.z), f2tf32(vv.w));
            *(uint4*)&Vs[r * VS_AT + d4] = vt;
        }
        __syncthreads();

        // ---- S = Q K^T : 8 n-frags of m16n8, k = 128 ----
        float sc[8][4];
#pragma unroll
        for (int ni = 0; ni < 8; ni++)
#pragma unroll
            for (int r = 0; r < 4; r++) sc[ni][r] = 0.f;

#pragma unroll
        for (int c = 0; c < 16; c++) {
#pragma unroll
            for (int ni = 0; ni < 8; ni++) {
                uint32_t b0 = Ks[(8 * ni + gid) * KS_AT + 8 * c + tig];
                uint32_t b1 = Ks[(8 * ni + gid) * KS_AT + 8 * c + tig + 4];
                asm volatile(
                    "mma.sync.aligned.m16n8k8.row.col.f32.tf32.tf32.f32 "
                    "{%0,%1,%2,%3}, {%4,%5,%6,%7}, {%8,%9}, {%0,%1,%2,%3};"
                    : "+f"(sc[ni][0]), "+f"(sc[ni][1]), "+f"(sc[ni][2]), "+f"(sc[ni][3])
                    : "r"(qa[c][0]), "r"(qa[c][1]), "r"(qa[c][2]), "r"(qa[c][3]),
                      "r"(b0), "r"(b1));
            }
        }

        // ---- softcap + window mask + exp; stash P(tf32); row partial sums ----
        const bool full = (k0 + 63 <= q0) && (q0 + 63 - k0 < WINDOW);
        float lp0 = 0.f, lp1 = 0.f;
#pragma unroll
        for (int ni = 0; ni < 8; ni++) {
#pragma unroll
            for (int r2 = 0; r2 < 2; r2++) {
#pragma unroll
                for (int cc = 0; cc < 2; cc++) {
                    const float raw = sc[ni][r2 * 2 + cc];
                    const int rg = q0 + qr0 + r2 * 8;
                    const int kg = k0 + 8 * ni + 2 * tig + cc;
                    float z = raw * (SCALING / SOFTCAP);
                    float t;
                    if (fabsf(z) < 0.3f) {
                        const float z2 = z * z;
                        t = z * (1.f + z2 * (-0.3333333333f +
                              z2 * (0.1333333333f - 0.05396825397f * z2)));
                    } else {
                        t = tanhf(z);  // essentially never taken (|z| <~ 0.12)
                    }
                    float p = __expf(t * SOFTCAP);
                    if (!full && (kg > rg || rg - kg >= WINDOW)) p = 0.f;
                    const uint32_t pt = f2tf32(p);
                    const float prnd = __uint_as_float(pt); // consistent num/denom
                    if (r2 == 0) lp0 += prnd; else lp1 += prnd;
                    Ps[(qr0 + r2 * 8) * PS_AT + 8 * ni + 2 * tig + cc] = pt;
                }
            }
        }
        lp0 += __shfl_xor_sync(0xffffffffu, lp0, 1);
        lp0 += __shfl_xor_sync(0xffffffffu, lp0, 2);
        lp1 += __shfl_xor_sync(0xffffffffu, lp1, 1);
        lp1 += __shfl_xor_sync(0xffffffffu, lp1, 2);
        lsum[0] += lp0;
        lsum[1] += lp1;
        __syncwarp();  // P rows for this warp produced & consumed intra-warp

        // ---- O += P V : 16 n-frags (d), k = 64 (keys) ----
#pragma unroll
        for (int c = 0; c < 8; c++) {
            uint32_t pa[4];
            pa[0] = Ps[qr0 * PS_AT + 8 * c + tig];
            pa[1] = Ps[(qr0 + 8) * PS_AT + 8 * c + tig];
            pa[2] = Ps[qr0 * PS_AT + 8 * c + tig + 4];
            pa[3] = Ps[(qr0 + 8) * PS_AT + 8 * c + tig + 4];
#pragma unroll
            for (int ni = 0; ni < 16; ni++) {
                uint32_t b0 = Vs[(8 * c + tig) * VS_AT + 8 * ni + gid];
                uint32_t b1 = Vs[(8 * c + tig + 4) * VS_AT + 8 * ni + gid];
                asm volatile(
                    "mma.sync.aligned.m16n8k8.row.col.f32.tf32.tf32.f32 "
                    "{%0,%1,%2,%3}, {%4,%5,%6,%7}, {%8,%9}, {%0,%1,%2,%3};"
                    : "+f"(oacc[ni][0]), "+f"(oacc[ni][1]),
                      "+f"(oacc[ni][2]), "+f"(oacc[ni][3])
                    : "r"(pa[0]), "r"(pa[1]), "r"(pa[2]), "r"(pa[3]),
                      "r"(b0), "r"(b1));
            }
        }
        __syncwarp();  // P reads done before next tile's stores
    }

    // ---- normalize + write ----
    const float inv0 = 1.0f / lsum[0];
    const float inv1 = 1.0f / lsum[1];
    float* out0 = AO + (size_t)(q0 + qr0) * (NH * HD) + h * HD;
    float* out1 = AO + (size_t)(q0 + qr0 + 8) * (NH * HD) + h * HD;
#pragma unroll
    for (int ni = 0; ni < 16; ni++) {
        const int n0 = 8 * ni + 2 * tig;
        *(float2*)(out0 + n0) = make_float2(oacc[ni][0] * inv0, oacc[ni][1] * inv0);
        *(float2*)(out1 + n0) = make_float2(oacc[ni][2] * inv1, oacc[ni][3] * inv1);
    }
}

// ---------------- launch ----------------
extern "C" void kernel_launch(void* const* d_in, const int* in_sizes, int n_in,
                              void* d_out, int out_size)
{
    const float* hs   = (const float*)d_in[0];
    const float* cosb = (const float*)d_in[1];
    const float* sinb = (const float*)d_in[2];
    // d_in[3] attention_mask: computed analytically, never read
    const float* Wq = (const float*)d_in[4];
    const float* Wk = (const float*)d_in[5];
    const float* Wv = (const float*)d_in[6];
    const float* Wo = (const float*)d_in[7];
    float* out = (float*)d_out;

    float *qp, *kp, *vp, *aop;
    cudaGetSymbolAddress((void**)&qp, g_Q);
    cudaGetSymbolAddress((void**)&kp, g_K);
    cudaGetSymbolAddress((void**)&vp, g_V);
    cudaGetSymbolAddress((void**)&aop, g_AO);

    dim3 blk(256);
    gemm_tf32<<<dim3((NH * HD) / 128, SEQ / 128), blk>>>(SEQ, NH * HD, HIDDEN, hs, Wq, qp);
    gemm_tf32<<<dim3((NKV * HD) / 128, SEQ / 128), blk>>>(SEQ, NKV * HD, HIDDEN, hs, Wk, kp);
    gemm_tf32<<<dim3((NKV * HD) / 128, SEQ / 128), blk>>>(SEQ, NKV * HD, HIDDEN, hs, Wv, vp);

    rope_kernel<<<SEQ, 256>>>(cosb, sinb);

    const size_t smem_bytes = (size_t)64 * (KS_AT + VS_AT + PS_AT) * sizeof(float);
    cudaFuncSetAttribute(attn_mma, cudaFuncAttributeMaxDynamicSharedMemorySize,
                         (int)smem_bytes);
    attn_mma<<<dim3(SEQ / 64, NH), 128, smem_bytes>>>(aop);

    gemm_tf32<<<dim3(HIDDEN / 128, SEQ / 128), blk>>>(SEQ, HIDDEN, NH * HD, aop, Wo, out);
}

// round 9
// speedup vs baseline: 3.6848x; 1.4758x over previous
#include <cuda_runtime.h>
#include <cstdint>

#define SEQ 4096
#define HIDDEN 2048
#define NH 16
#define NKV 8
#define HD 128
#define WINDOW 1024
#define SCALING 0.08838834764831845f  /* 128^-0.5 */
#define SOFTCAP 50.0f

// ---------------- scratch (no allocations allowed) ----------------
__device__ float g_Q[SEQ * NH * HD];    // 32 MB
__device__ float g_K[SEQ * NKV * HD];   // 16 MB
__device__ float g_V[SEQ * NKV * HD];   // 16 MB
__device__ float g_AO[SEQ * NH * HD];   // 32 MB

__device__ __forceinline__ uint32_t f2tf32(float x) {
    uint32_t r;
    asm("cvt.rna.tf32.f32 %0, %1;" : "=r"(r) : "f"(x));
    return r;
}

__device__ __forceinline__ void cp16(uint32_t s, const void* g) {
    asm volatile("cp.async.cg.shared.global [%0], [%1], 16;" :: "r"(s), "l"(g) : "memory");
}
__device__ __forceinline__ void cp_commit() {
    asm volatile("cp.async.commit_group;" ::: "memory");
}
__device__ __forceinline__ void cp_wait1() {
    asm volatile("cp.async.wait_group 1;" ::: "memory");
}

// ---------------- cp.async pipelined TF32 GEMM core ----------------
// C[128,128] block of C[M,N] = A[M,K] @ B[K,N], row-major.
// 256 thr (8 warps, 2x4), BK=32, 2-stage cp.async ring.
// As [m][k] stride 36 (mod32=4 -> A frags conflict-free)
// Bs [k][n] stride 136 (mod32=8 -> B frags conflict-free)
#define GAS_W 36
#define GBS_W 136
#define GA_STAGE (128 * GAS_W)          // 4608 words
#define GB_STAGE (32 * GBS_W)           // 4352 words
#define GSTAGE_W (GA_STAGE + GB_STAGE)  // 8960 words
#define GSMEM_BYTES (2 * GSTAGE_W * 4)  // 71680 B

__device__ __forceinline__ void gemm_core(
    const float* __restrict__ Ab,   // A + by*128*K
    const float* __restrict__ Bb,   // B + bx*128
    float* __restrict__ Cb,         // C + by*128*N + bx*128
    int N, int K)
{
    extern __shared__ float smem[];
    const uint32_t sb = (uint32_t)__cvta_generic_to_shared(smem);

    const int tid  = threadIdx.x;
    const int lane = tid & 31;
    const int gid  = lane >> 2;
    const int tig  = lane & 3;
    const int wid  = tid >> 5;
    const int wm0  = (wid >> 2) * 64;
    const int wn0  = (wid & 3) * 32;

    float c[4][4][4];
#pragma unroll
    for (int mi = 0; mi < 4; mi++)
#pragma unroll
        for (int ni = 0; ni < 4; ni++)
#pragma unroll
            for (int r = 0; r < 4; r++) c[mi][ni][r] = 0.f;

    const int KT = K / 32;

    auto issue = [&](int stg, int k0) {
        const uint32_t as = sb + (uint32_t)stg * GSTAGE_W * 4;
        const uint32_t bs = as + GA_STAGE * 4;
#pragma unroll
        for (int i = 0; i < 4; i++) {
            const int t = tid + i * 256;
            const int m = t >> 3, j = t & 7;
            cp16(as + (uint32_t)(m * GAS_W + 4 * j) * 4,
                 Ab + (size_t)m * K + k0 + 4 * j);
        }
#pragma unroll
        for (int i = 0; i < 4; i++) {
            const int t = tid + i * 256;
            const int r = t >> 5, cc = t & 31;
            cp16(bs + (uint32_t)(r * GBS_W + 4 * cc) * 4,
                 Bb + (size_t)(k0 + r) * N + 4 * cc);
        }
        cp_commit();
    };

    issue(0, 0);

    for (int kt = 0; kt < KT; kt++) {
        if (kt + 1 < KT) issue((kt + 1) & 1, (kt + 1) * 32);
        else             cp_commit();          // empty group keeps wait count honest
        cp_wait1();
        __syncthreads();

        const float* As = smem + (kt & 1) * GSTAGE_W;
        const float* Bs = As + GA_STAGE;

#pragma unroll
        for (int kk = 0; kk < 4; kk++) {
            const int kb = kk * 8;
            uint32_t aR[4][4], bR[4][2];
#pragma unroll
            for (int mi = 0; mi < 4; mi++) {
                const int m0 = wm0 + mi * 16;
                aR[mi][0] = f2tf32(As[(m0 + gid) * GAS_W + kb + tig]);
                aR[mi][1] = f2tf32(As[(m0 + gid + 8) * GAS_W + kb + tig]);
                aR[mi][2] = f2tf32(As[(m0 + gid) * GAS_W + kb + tig + 4]);
                aR[mi][3] = f2tf32(As[(m0 + gid + 8) * GAS_W + kb + tig + 4]);
            }
#pragma unroll
            for (int ni = 0; ni < 4; ni++) {
                const int n0 = wn0 + ni * 8;
                bR[ni][0] = f2tf32(Bs[(kb + tig) * GBS_W + n0 + gid]);
                bR[ni][1] = f2tf32(Bs[(kb + tig + 4) * GBS_W + n0 + gid]);
            }
#pragma unroll
            for (int mi = 0; mi < 4; mi++)
#pragma unroll
                for (int ni = 0; ni < 4; ni++) {
                    asm volatile(
                        "mma.sync.aligned.m16n8k8.row.col.f32.tf32.tf32.f32 "
                        "{%0,%1,%2,%3}, {%4,%5,%6,%7}, {%8,%9}, {%0,%1,%2,%3};"
                        : "+f"(c[mi][ni][0]), "+f"(c[mi][ni][1]),
                          "+f"(c[mi][ni][2]), "+f"(c[mi][ni][3])
                        : "r"(aR[mi][0]), "r"(aR[mi][1]), "r"(aR[mi][2]), "r"(aR[mi][3]),
                          "r"(bR[ni][0]), "r"(bR[ni][1]));
                }
        }
        __syncthreads();   // all reads of this stage done before it is re-filled
    }

#pragma unroll
    for (int mi = 0; mi < 4; mi++) {
        const int m0 = wm0 + mi * 16;
#pragma unroll
        for (int ni = 0; ni < 4; ni++) {
            const int n0 = wn0 + ni * 8 + tig * 2;
            *(float2*)(Cb + (size_t)(m0 + gid) * N + n0) =
                make_float2(c[mi][ni][0], c[mi][ni][1]);
            *(float2*)(Cb + (size_t)(m0 + gid + 8) * N + n0) =
                make_float2(c[mi][ni][2], c[mi][ni][3]);
        }
    }
}

// fused QKV: grid (32, 32); bx<16 -> Q, 16..23 -> K, 24..31 -> V
__global__ __launch_bounds__(256, 2) void qkv_gemm(
    const float* __restrict__ X,
    const float* __restrict__ Wq, const float* __restrict__ Wk,
    const float* __restrict__ Wv)
{
    const int bx = blockIdx.x, by = blockIdx.y;
    const float* B; float* C; int N; int lbx;
    if (bx < 16)      { B = Wq; C = g_Q; N = NH * HD;  lbx = bx; }
    else if (bx < 24) { B = Wk; C = g_K; N = NKV * HD; lbx = bx - 16; }
    else              { B = Wv; C = g_V; N = NKV * HD; lbx = bx - 24; }
    gemm_core(X + (size_t)by * 128 * HIDDEN,
              B + (size_t)lbx * 128,
              C + (size_t)by * 128 * N + (size_t)lbx * 128,
              N, HIDDEN);
}

__global__ __launch_bounds__(256, 2) void wo_gemm(
    const float* __restrict__ Wo, float* __restrict__ out)
{
    const int bx = blockIdx.x, by = blockIdx.y;
    gemm_core(g_AO + (size_t)by * 128 * (NH * HD),
              Wo + (size_t)bx * 128,
              out + (size_t)by * 128 * HIDDEN + (size_t)bx * 128,
              HIDDEN, NH * HD);
}

// ---------------- RoPE (in place on g_Q, g_K) ----------------
__global__ void rope_kernel(const float* __restrict__ cosb,
                            const float* __restrict__ sinb)
{
    const int s = blockIdx.x;
    const float* cs = cosb + (size_t)s * HD;
    const float* sn = sinb + (size_t)s * HD;
    for (int idx = threadIdx.x; idx < (NH + NKV) * 64; idx += blockDim.x) {
        const int head = idx >> 6;
        const int d = idx & 63;
        const float c = cs[d];
        const float sv = sn[d];
        float* base;
        if (head < NH)
            base = g_Q + (size_t)s * (NH * HD) + head * HD;
        else
            base = g_K + (size_t)s * (NKV * HD) + (head - NH) * HD;
        const float x1 = base[d];
        const float x2 = base[d + 64];
        base[d]      = x1 * c - x2 * sv;
        base[d + 64] = x2 * c + x1 * sv;
    }
}

// ---------------- TF32 tensor-core flash attention ----------------
// Writes g_AO directly (device symbol referenced in device code — no host-side
// symbol address passing).
#define KS_AT 132   // mod 32 = 4
#define VS_AT 136   // mod 32 = 8
#define PS_AT 68    // mod 32 = 4

extern __shared__ float sm_attn[];

__global__ __launch_bounds__(128, 2) void attn_mma()
{
    float*    Qs = sm_attn;
    uint32_t* Ks = (uint32_t*)sm_attn;
    uint32_t* Vs = (uint32_t*)(sm_attn + 64 * KS_AT);
    uint32_t* Ps = (uint32_t*)(sm_attn + 64 * (KS_AT + VS_AT));

    const int qb = blockIdx.x;
    const int h  = blockIdx.y;
    const int kvh = h >> 1;
    const int q0 = qb * 64;
    const int tid = threadIdx.x;
    const int lane = tid & 31;
    const int w = tid >> 5;
    const int gid = lane >> 2;
    const int tig = lane & 3;

    const float* Qg = g_Q + (size_t)q0 * (NH * HD) + h * HD;
    for (int i = tid; i < 64 * HD / 4; i += 128) {
        const int r = i >> 5;
        const int d4 = (i & 31) * 4;
        float4 v = *(const float4*)(Qg + (size_t)r * (NH * HD) + d4);
        *(float4*)&Qs[r * KS_AT + d4] = v;
    }
    __syncthreads();

    uint32_t qa[16][4];
    const int qr0 = 16 * w + gid;
#pragma unroll
    for (int c = 0; c < 16; c++) {
        qa[c][0] = f2tf32(Qs[qr0 * KS_AT + 8 * c + tig]);
        qa[c][1] = f2tf32(Qs[(qr0 + 8) * KS_AT + 8 * c + tig]);
        qa[c][2] = f2tf32(Qs[qr0 * KS_AT + 8 * c + tig + 4]);
        qa[c][3] = f2tf32(Qs[(qr0 + 8) * KS_AT + 8 * c + tig + 4]);
    }

    float oacc[16][4];
#pragma unroll
    for (int ni = 0; ni < 16; ni++)
#pragma unroll
        for (int r = 0; r < 4; r++) oacc[ni][r] = 0.f;
    float lsum[2] = {0.f, 0.f};

    int lo = q0 - (WINDOW - 1);
    if (lo < 0) lo = 0;
    const int kb_lo = lo / 64;

    for (int kb = kb_lo; kb <= qb; kb++) {
        const int k0 = kb * 64;
        const float* Kg = g_K + (size_t)k0 * (NKV * HD) + kvh * HD;
        const float* Vg = g_V + (size_t)k0 * (NKV * HD) + kvh * HD;

        __syncthreads();
        for (int i = tid; i < 64 * HD / 4; i += 128) {
            const int r = i >> 5;
            const int d4 = (i & 31) * 4;
            float4 kv = *(const float4*)(Kg + (size_t)r * (NKV * HD) + d4);
            uint4 kt = make_uint4(f2tf32(kv.x), f2tf32(kv.y), f2tf32(kv.z), f2tf32(kv.w));
            *(uint4*)&Ks[r * KS_AT + d4] = kt;
            float4 vv = *(const float4*)(Vg + (size_t)r * (NKV * HD) + d4);
            uint4 vt = make_uint4(f2tf32(vv.x), f2tf32(vv.y), f2tf32(vv.z), f2tf32(vv.w));
            *(uint4*)&Vs[r * VS_AT + d4] = vt;
        }
        __syncthreads();

        float sc[8][4];
#pragma unroll
        for (int ni = 0; ni < 8; ni++)
#pragma unroll
            for (int r = 0; r < 4; r++) sc[ni][r] = 0.f;

#pragma unroll
        for (int c = 0; c < 16; c++) {
#pragma unroll
            for (int ni = 0; ni < 8; ni++) {
                uint32_t b0 = Ks[(8 * ni + gid) * KS_AT + 8 * c + tig];
                uint32_t b1 = Ks[(8 * ni + gid) * KS_AT + 8 * c + tig + 4];
                asm volatile(
                    "mma.sync.aligned.m16n8k8.row.col.f32.tf32.tf32.f32 "
                    "{%0,%1,%2,%3}, {%4,%5,%6,%7}, {%8,%9}, {%0,%1,%2,%3};"
                    : "+f"(sc[ni][0]), "+f"(sc[ni][1]), "+f"(sc[ni][2]), "+f"(sc[ni][3])
                    : "r"(qa[c][0]), "r"(qa[c][1]), "r"(qa[c][2]), "r"(qa[c][3]),
                      "r"(b0), "r"(b1));
            }
        }

        const bool full = (k0 + 63 <= q0) && (q0 + 63 - k0 < WINDOW);
        float lp0 = 0.f, lp1 = 0.f;
#pragma unroll
        for (int ni = 0; ni < 8; ni++) {
#pragma unroll
            for (int r2 = 0; r2 < 2; r2++) {
#pragma unroll
                for (int cc = 0; cc < 2; cc++) {
                    const float raw = sc[ni][r2 * 2 + cc];
                    const int rg = q0 + qr0 + r2 * 8;
                    const int kg = k0 + 8 * ni + 2 * tig + cc;
                    float z = raw * (SCALING / SOFTCAP);
                    float t;
                    if (fabsf(z) < 0.3f) {
                        const float z2 = z * z;
                        t = z * (1.f + z2 * (-0.3333333333f +
                              z2 * (0.1333333333f - 0.05396825397f * z2)));
                    } else {
                        t = tanhf(z);
                    }
                    float p = __expf(t * SOFTCAP);
                    if (!full && (kg > rg || rg - kg >= WINDOW)) p = 0.f;
                    const uint32_t pt = f2tf32(p);
                    const float prnd = __uint_as_float(pt);
                    if (r2 == 0) lp0 += prnd; else lp1 += prnd;
                    Ps[(qr0 + r2 * 8) * PS_AT + 8 * ni + 2 * tig + cc] = pt;
                }
            }
        }
        lp0 += __shfl_xor_sync(0xffffffffu, lp0, 1);
        lp0 += __shfl_xor_sync(0xffffffffu, lp0, 2);
        lp1 += __shfl_xor_sync(0xffffffffu, lp1, 1);
        lp1 += __shfl_xor_sync(0xffffffffu, lp1, 2);
        lsum[0] += lp0;
        lsum[1] += lp1;
        __syncwarp();

#pragma unroll
        for (int c = 0; c < 8; c++) {
            uint32_t pa[4];
            pa[0] = Ps[qr0 * PS_AT + 8 * c + tig];
            pa[1] = Ps[(qr0 + 8) * PS_AT + 8 * c + tig];
            pa[2] = Ps[qr0 * PS_AT + 8 * c + tig + 4];
            pa[3] = Ps[(qr0 + 8) * PS_AT + 8 * c + tig + 4];
#pragma unroll
            for (int ni = 0; ni < 16; ni++) {
                uint32_t b0 = Vs[(8 * c + tig) * VS_AT + 8 * ni + gid];
                uint32_t b1 = Vs[(8 * c + tig + 4) * VS_AT + 8 * ni + gid];
                asm volatile(
                    "mma.sync.aligned.m16n8k8.row.col.f32.tf32.tf32.f32 "
                    "{%0,%1,%2,%3}, {%4,%5,%6,%7}, {%8,%9}, {%0,%1,%2,%3};"
                    : "+f"(oacc[ni][0]), "+f"(oacc[ni][1]),
                      "+f"(oacc[ni][2]), "+f"(oacc[ni][3])
                    : "r"(pa[0]), "r"(pa[1]), "r"(pa[2]), "r"(pa[3]),
                      "r"(b0), "r"(b1));
            }
        }
        __syncwarp();
    }

    const float inv0 = 1.0f / lsum[0];
    const float inv1 = 1.0f / lsum[1];
    float* out0 = g_AO + (size_t)(q0 + qr0) * (NH * HD) + h * HD;
    float* out1 = g_AO + (size_t)(q0 + qr0 + 8) * (NH * HD) + h * HD;
#pragma unroll
    for (int ni = 0; ni < 16; ni++) {
        const int n0 = 8 * ni + 2 * tig;
        *(float2*)(out0 + n0) = make_float2(oacc[ni][0] * inv0, oacc[ni][1] * inv0);
        *(float2*)(out1 + n0) = make_float2(oacc[ni][2] * inv1, oacc[ni][3] * inv1);
    }
}

// ---------------- launch ----------------
extern "C" void kernel_launch(void* const* d_in, const int* in_sizes, int n_in,
                              void* d_out, int out_size)
{
    const float* hs   = (const float*)d_in[0];
    const float* cosb = (const float*)d_in[1];
    const float* sinb = (const float*)d_in[2];
    // d_in[3] attention_mask: computed analytically, never read
    const float* Wq = (const float*)d_in[4];
    const float* Wk = (const float*)d_in[5];
    const float* Wv = (const float*)d_in[6];
    const float* Wo = (const float*)d_in[7];
    float* out = (float*)d_out;

    cudaFuncSetAttribute(qkv_gemm, cudaFuncAttributeMaxDynamicSharedMemorySize, GSMEM_BYTES);
    cudaFuncSetAttribute(wo_gemm, cudaFuncAttributeMaxDynamicSharedMemorySize, GSMEM_BYTES);

    qkv_gemm<<<dim3(32, SEQ / 128), 256, GSMEM_BYTES>>>(hs, Wq, Wk, Wv);

    rope_kernel<<<SEQ, 256>>>(cosb, sinb);

    const size_t smem_attn = (size_t)64 * (KS_AT + VS_AT + PS_AT) * sizeof(float);
    cudaFuncSetAttribute(attn_mma, cudaFuncAttributeMaxDynamicSharedMemorySize,
                         (int)smem_attn);
    attn_mma<<<dim3(SEQ / 64, NH), 128, smem_attn>>>();

    wo_gemm<<<dim3(HIDDEN / 128, SEQ / 128), 256, GSMEM_BYTES>>>(Wo, out);
}